// round 16
// baseline (speedup 1.0000x reference)
#include <cuda_runtime.h>
#include <cuda_fp16.h>
#include <cstddef>

// Problem constants
#define H 256
#define W 256
#define KW 129          // rfft bins along W
#define B_ 16
#define C_ 32
#define O_ 32
#define NIMG_X (B_*C_)  // 512
#define NIMG_W (O_*C_)  // 1024
#define NIMG_Y (B_*O_)  // 512

// ---------------- scratch (static device globals; allocation-free) ----------
__device__ __half2 g_xr[(size_t)KW * NIMG_X * H];
__device__ __half2 g_wr[(size_t)KW * NIMG_W * H];
__device__ __half2 g_xf[(size_t)H * KW * NIMG_X];
__device__ __half2 g_wf[(size_t)H * KW * NIMG_W];
__device__ __half2 g_yf[(size_t)H * KW * NIMG_Y];
__device__ __half2 g_yr[(size_t)KW * NIMG_Y * H];
__device__ float2  g_twd[256];   // W_256^i forward twiddles

__device__ __forceinline__ float2 cmulf(float2 a, float2 b) {
    return make_float2(fmaf(a.x, b.x, -a.y * b.y), fmaf(a.x, b.y, a.y * b.x));
}
__device__ __forceinline__ __half2 f2h(float2 v) { return __floats2half2_rn(v.x, v.y); }
__device__ __forceinline__ float2 h2f(__half2 v) { return __half22float2(v); }
__device__ __forceinline__ unsigned h2bits(__half2 v) { return *reinterpret_cast<unsigned*>(&v); }
__device__ __forceinline__ __half2 bits2h(unsigned u) { return *reinterpret_cast<__half2*>(&u); }
// streaming (last-use) half2 load
__device__ __forceinline__ __half2 ldcs_h2(const __half2* p) {
    unsigned u = __ldcs((const unsigned*)p);
    return bits2h(u);
}

// ---------------- K0: build twiddle table once per call ---------------------
__global__ void k_twd() {
    const int i = threadIdx.x;
    float sn, cs;
    sincosf(-6.283185307179586f * (float)i / 256.0f, &sn, &cs);
    g_twd[i] = make_float2(cs, sn);
}

// ---------------- in-register FFT-16 (Stockham radix-2, 4 stages) -----------
template <bool INV>
__device__ __forceinline__ void fft16r(float2* a) {
    const float TR[8] = { 1.f,  0.9238795325112867f,  0.7071067811865476f,  0.3826834323650898f,
                          0.f, -0.3826834323650898f, -0.7071067811865476f, -0.9238795325112867f };
    const float TI[8] = { 0.f, -0.3826834323650898f, -0.7071067811865476f, -0.9238795325112867f,
                         -1.f, -0.9238795325112867f, -0.7071067811865476f, -0.3826834323650898f };
    float2 b[16];
    float2 *s = a, *d = b;
#pragma unroll
    for (int st = 0; st < 4; st++) {
        const int S = 1 << st;
#pragma unroll
        for (int t = 0; t < 8; t++) {
            const int j = t & ~(S - 1);
            const float wr = TR[j];
            const float wi = INV ? -TI[j] : TI[j];
            float2 u = s[t], v = s[t + 8];
            float2 sum = make_float2(u.x + v.x, u.y + v.y);
            float2 dif = make_float2(u.x - v.x, u.y - v.y);
            d[t + j]     = sum;
            d[t + j + S] = make_float2(fmaf(dif.x, wr, -dif.y * wi),
                                       fmaf(dif.x, wi,  dif.y * wr));
        }
        float2* tmp = s; s = d; d = tmp;
    }
}

// ---------------- FFT-256 on registers: 16 threads x 16 points --------------
template <bool INV>
__device__ __forceinline__ void fft256_regs(float2* a, float2* S,
                                            const float2* twd, int row, int t) {
    fft16r<INV>(a);
    // k2=0 multiplier is exactly (1,0) -> identity; skip (bit-identical).
#pragma unroll
    for (int k2 = 1; k2 < 16; k2++) {
        float2 w = twd[t * k2];
        if (INV) w.y = -w.y;
        a[k2] = cmulf(a[k2], w);
    }
    float2* Sr = S + row * 272;
    __syncwarp();
#pragma unroll
    for (int k2 = 0; k2 < 16; k2++) Sr[t * 17 + k2] = a[k2];
    __syncwarp();
#pragma unroll
    for (int n1 = 0; n1 < 16; n1++) a[n1] = Sr[n1 * 17 + t];
    __syncwarp();
    fft16r<INV>(a);
}

// ---------------- K1: packed row FFT (2 real rows per complex FFT) ----------
__global__ void __launch_bounds__(256) k_rowfft(const float* __restrict__ in,
                                                __half2* __restrict__ out, int nimg) {
    __shared__ float2 S[4352];
    __shared__ float2 twd[256];
    const int tid = threadIdx.x, row = tid >> 4, t = tid & 15;
    const int img = blockIdx.x >> 3, h0 = (blockIdx.x & 7) << 5;
    cudaGridDependencySynchronize();     // PDL: wait for producer before reads
    twd[tid] = g_twd[tid];
    const float* pa = in + ((size_t)img * H + h0 + 2 * row) * W + t;
    const float* pb = pa + W;
    float2 a[16];
#pragma unroll
    for (int q = 0; q < 16; q++) a[q] = make_float2(__ldcs(pa + q * 16), __ldcs(pb + q * 16));
    __syncthreads();
    fft256_regs<false>(a, S, twd, row, t);
    __syncthreads();
#pragma unroll
    for (int k1 = 0; k1 < 16; k1++) S[(k1 * 16 + t) * 17 + row] = a[k1];
    __syncthreads();
    const size_t ob = (size_t)img * H + h0;
    // Vectorized unpack: even/odd h-rows share Z/Zc -> one 8B store per pair.
    for (int i = tid; i < KW * 16; i += 256) {
        const int kw_ = i >> 4, r = i & 15;
        const float2 Z  = S[kw_ * 17 + r];
        const float2 Zc = S[((256 - kw_) & 255) * 17 + r];
        const __half2 he = f2h(make_float2((Z.x + Zc.x) * 0.5f, (Z.y - Zc.y) * 0.5f));
        const __half2 ho = f2h(make_float2((Z.y + Zc.y) * 0.5f, (Zc.x - Z.x) * 0.5f));
        uint2 v; v.x = h2bits(he); v.y = h2bits(ho);
        *reinterpret_cast<uint2*>(&out[(size_t)kw_ * nimg * H + ob + 2 * r]) = v;
    }
}

// ---------------- K2: column FFT -> bin-major [kh][KW][nimg] (fp16) ---------
__global__ void __launch_bounds__(256) k_colfft(const __half2* __restrict__ in,
                                                __half2* __restrict__ out, int nimg) {
    __shared__ float2 S[4352];
    __shared__ float2 twd[256];
    const int tid = threadIdx.x, row = tid >> 4, t = tid & 15;
    const int kw = blockIdx.x, img0 = blockIdx.y << 4;
    cudaGridDependencySynchronize();
    twd[tid] = g_twd[tid];
    const __half2* src = in + ((size_t)kw * nimg + img0 + row) * H + t;
    float2 a[16];
#pragma unroll
    for (int q = 0; q < 16; q++) a[q] = h2f(ldcs_h2(src + q * 16));
    __syncthreads();
    fft256_regs<false>(a, S, twd, row, t);
    __syncthreads();
#pragma unroll
    for (int k1 = 0; k1 < 16; k1++) S[(k1 * 16 + t) * 17 + row] = a[k1];
    __syncthreads();
    // Vectorized: 2 images per thread, one 8B store.
    for (int i = tid; i < 2048; i += 256) {
        const int kh = i >> 3, im = (i & 7) << 1;
        uint2 v;
        v.x = h2bits(f2h(S[kh * 17 + im]));
        v.y = h2bits(f2h(S[kh * 17 + im + 1]));
        *reinterpret_cast<uint2*>(&out[((size_t)kh * KW + kw) * nimg + img0 + im]) = v;
    }
}

// ---------------- K3: bingemm v5 — cp.async double-buffered pipeline --------
__device__ __forceinline__ void mma16816(float* c, const unsigned* a, unsigned b0, unsigned b1) {
    asm volatile("mma.sync.aligned.m16n8k16.row.col.f32.f16.f16.f32 "
                 "{%0,%1,%2,%3}, {%4,%5,%6,%7}, {%8,%9}, {%0,%1,%2,%3};"
                 : "+f"(c[0]), "+f"(c[1]), "+f"(c[2]), "+f"(c[3])
                 : "r"(a[0]), "r"(a[1]), "r"(a[2]), "r"(a[3]), "r"(b0), "r"(b1));
}

#define BG_XS_U 576          // per-bin x region (unsigned), pitch 36
#define BG_WS_U 1152         // per-bin w region (unsigned), pitch 36
#define BG_WS_BASE (2 * 4 * BG_XS_U)             // = 4608 unsigned
#define BG_SMEM_BYTES ((2 * 4 * (BG_XS_U + BG_WS_U)) * 4)   // 55296 B

__global__ void __launch_bounds__(256) k_bingemm(const __half2* __restrict__ xf,
                                                 const __half2* __restrict__ wf,
                                                 __half2* __restrict__ yf) {
    extern __shared__ __align__(16) unsigned sm[];
    unsigned* xs = sm;
    unsigned* ws = sm + BG_WS_BASE;
    const unsigned smem_base = (unsigned)__cvta_generic_to_shared(sm);
    const int tid = threadIdx.x;
    const size_t gbin0 = (size_t)blockIdx.x * 16;
    cudaGridDependencySynchronize();

    auto issue = [&](int ch) {
        const int buf = ch & 1;
        const char* xg = (const char*)(xf + (gbin0 + ch * 4) * NIMG_X);
        const char* wg = (const char*)(wf + (gbin0 + ch * 4) * NIMG_W);
        for (int i = tid; i < 512; i += 256) {
            const int lb = i >> 7, jj = (i & 127) << 2;
            const unsigned soff = ((buf * 4 + lb) * BG_XS_U + (jj >> 5) * 36 + (jj & 31)) * 4;
            asm volatile("cp.async.cg.shared.global [%0], [%1], 16;"
                         :: "r"(smem_base + soff), "l"(xg + lb * 2048 + jj * 4) : "memory");
        }
        for (int i = tid; i < 1024; i += 256) {
            const int lb = i >> 8, jj = (i & 255) << 2;
            const unsigned soff = (BG_WS_BASE + (buf * 4 + lb) * BG_WS_U
                                   + (jj >> 5) * 36 + (jj & 31)) * 4;
            asm volatile("cp.async.cg.shared.global [%0], [%1], 16;"
                         :: "r"(smem_base + soff), "l"(wg + lb * 4096 + jj * 4) : "memory");
        }
        asm volatile("cp.async.commit_group;" ::: "memory");
    };

    issue(0);
    issue(1);

    const int wp = tid >> 6;             // bin-in-chunk 0..3
    const int sub = (tid >> 5) & 1;      // which half of the ot tiles
    const int lane = tid & 31, r = lane >> 2, q = lane & 3;

    for (int ch = 0; ch < 4; ch++) {
        const int buf = ch & 1;
        if (ch < 3) asm volatile("cp.async.wait_group 1;" ::: "memory");
        else        asm volatile("cp.async.wait_group 0;" ::: "memory");
        __syncthreads();

        unsigned* X = xs + (buf * 4 + wp) * BG_XS_U;
        const unsigned* Wm = ws + (buf * 4 + wp) * BG_WS_U;
        float cre[2][4] = {{0}}, cim[2][4] = {{0}};
#pragma unroll
        for (int kc = 0; kc < 4; kc++) {
            unsigned a[4];
            a[0] = X[r * 36 + kc * 8 + q];
            a[1] = X[(r + 8) * 36 + kc * 8 + q];
            a[2] = X[r * 36 + kc * 8 + 4 + q];
            a[3] = X[(r + 8) * 36 + kc * 8 + 4 + q];
#pragma unroll
            for (int oti = 0; oti < 2; oti++) {
                const int ot = sub * 2 + oti;
                const unsigned w0 = Wm[(ot * 8 + r) * 36 + kc * 8 + q];
                const unsigned w1 = Wm[(ot * 8 + r) * 36 + kc * 8 + 4 + q];
                mma16816(cre[oti], a, w0 ^ 0x80000000u, w1 ^ 0x80000000u);  // (wr,-wi)
                mma16816(cim[oti], a, __byte_perm(w0, w0, 0x1032),          // (wi,wr)
                                       __byte_perm(w1, w1, 0x1032));
            }
        }
        __syncthreads();   // all fragment reads of this buffer done
        // Stage C into the (dead) x region of this buffer, stride 33.
#pragma unroll
        for (int oti = 0; oti < 2; oti++) {
            const int ot = sub * 2 + oti;
            const int o0 = ot * 8 + 2 * q;
            X[r * 33 + o0]           = h2bits(f2h(make_float2(cre[oti][0], cim[oti][0])));
            X[r * 33 + o0 + 1]       = h2bits(f2h(make_float2(cre[oti][1], cim[oti][1])));
            X[(r + 8) * 33 + o0]     = h2bits(f2h(make_float2(cre[oti][2], cim[oti][2])));
            X[(r + 8) * 33 + o0 + 1] = h2bits(f2h(make_float2(cre[oti][3], cim[oti][3])));
        }
        __syncthreads();
        unsigned* yg = (unsigned*)(yf + (gbin0 + ch * 4) * NIMG_Y);
        for (int i = tid; i < 512; i += 256) {
            const int lb = i >> 7, jj = (i & 127) << 2;
            const int base = (buf * 4 + lb) * BG_XS_U + (jj >> 5) * 33 + (jj & 31);
            uint4 v;
            v.x = xs[base];
            v.y = xs[base + 1];
            v.z = xs[base + 2];
            v.w = xs[base + 3];
            *reinterpret_cast<uint4*>(yg + lb * 512 + jj) = v;
        }
        __syncthreads();   // copy-out reads done before this buffer is refilled
        if (ch + 2 < 4) issue(ch + 2);
    }
}

// ---------------- K4: inverse column FFT -> [kw][nimg][h], scale 1/256 ------
__global__ void __launch_bounds__(256) k_icolfft(const __half2* __restrict__ in,
                                                 __half2* __restrict__ out, int nimg) {
    __shared__ float2 S[4352];
    __shared__ float2 twd[256];
    const int tid = threadIdx.x, row = tid >> 4, t = tid & 15;
    const int kw = blockIdx.x, img0 = blockIdx.y << 4;
    cudaGridDependencySynchronize();
    twd[tid] = g_twd[tid];
    // Vectorized 8B input loads (2 images per thread).
    for (int i = tid; i < 2048; i += 256) {
        const int kh = i >> 3, im = (i & 7) << 1;
        const uint2 u = __ldcs((const uint2*)(in + ((size_t)kh * KW + kw) * nimg + img0 + im));
        S[kh * 17 + im]     = h2f(bits2h(u.x));
        S[kh * 17 + im + 1] = h2f(bits2h(u.y));
    }
    __syncthreads();
    float2 a[16];
#pragma unroll
    for (int q = 0; q < 16; q++) a[q] = S[(q * 16 + t) * 17 + row];
    __syncthreads();
    fft256_regs<true>(a, S, twd, row, t);
    __syncthreads();
    const float sc = 1.0f / 256.0f;
#pragma unroll
    for (int k1 = 0; k1 < 16; k1++)
        S[row * 256 + k1 * 16 + t] = make_float2(a[k1].x * sc, a[k1].y * sc);
    __syncthreads();
    // Vectorized: 2 h per thread (16B smem read, 8B gmem store).
    for (int i = tid; i < 2048; i += 256) {
        const int im = i >> 7, h = (i & 127) << 1;
        const float4 vv = *reinterpret_cast<const float4*>(&S[im * 256 + h]);
        uint2 v;
        v.x = h2bits(f2h(make_float2(vv.x, vv.y)));
        v.y = h2bits(f2h(make_float2(vv.z, vv.w)));
        *reinterpret_cast<uint2*>(&out[((size_t)kw * nimg + img0 + im) * H + h]) = v;
    }
}

// ---------------- K5: packed inverse row FFT (2 real rows per iFFT) ---------
__global__ void __launch_bounds__(256) k_irowfft(const __half2* __restrict__ in,
                                                 float* __restrict__ out, int nimg) {
    __shared__ float2 S[4352];
    __shared__ float2 twd[256];
    const int tid = threadIdx.x, row = tid >> 4, t = tid & 15;
    const int img = blockIdx.x >> 3, h0 = (blockIdx.x & 7) << 5;
    cudaGridDependencySynchronize();
    twd[tid] = g_twd[tid];
    // Vectorized 8B input loads (2 hh per thread).
    for (int i = tid; i < KW * 16; i += 256) {
        const int kw_ = i >> 4, hh = (i & 15) << 1;
        const uint2 u = __ldcs((const uint2*)(in + (size_t)kw_ * nimg * H + (size_t)img * H + h0 + hh));
        S[kw_ * 33 + hh]     = h2f(bits2h(u.x));
        S[kw_ * 33 + hh + 1] = h2f(bits2h(u.y));
    }
    __syncthreads();
    float2 a[16];
#pragma unroll
    for (int q = 0; q < 16; q++) {
        const int n = q * 16 + t;
        if (n <= 128) {
            const float2 ya = S[n * 33 + 2 * row];
            const float2 yb = S[n * 33 + 2 * row + 1];
            a[q] = make_float2(ya.x - yb.y, ya.y + yb.x);        // Ya + i*Yb
        } else {
            const int m = 256 - n;
            const float2 ya = S[m * 33 + 2 * row];
            const float2 yb = S[m * 33 + 2 * row + 1];
            a[q] = make_float2(ya.x + yb.y, yb.x - ya.y);        // conj(Ya)+i*conj(Yb)
        }
    }
    __syncthreads();
    fft256_regs<true>(a, S, twd, row, t);
    __syncthreads();
    float* Sf = (float*)S;
    const float sc = 1.0f / 256.0f;
#pragma unroll
    for (int k1 = 0; k1 < 16; k1++) {
        const int idx = k1 * 16 + t;
        Sf[(2 * row) * 256 + idx]     = a[k1].x * sc;
        Sf[(2 * row + 1) * 256 + idx] = a[k1].y * sc;
    }
    __syncthreads();
    const size_t ob = ((size_t)img * H + h0) * W;
    // Vectorized 16B output stores.
    for (int i = tid; i < 2048; i += 256) {
        const int base = i << 2;
        const float4 v = *reinterpret_cast<const float4*>(&Sf[base]);
        __stcs((float4*)(out + ob + (size_t)(base >> 8) * W + (base & 255)), v);
    }
}

// ---------------------------------------------------------------------------
extern "C" void kernel_launch(void* const* d_in, const int* in_sizes, int n_in,
                              void* d_out, int out_size) {
    (void)in_sizes; (void)n_in; (void)out_size;
    const float* x = (const float*)d_in[0];   // (B,C,H,W)
    const float* w = (const float*)d_in[1];   // (O,C,H,W)
    float* out = (float*)d_out;               // (B,O,H,W)

    __half2 *xr, *wr, *xf, *wf, *yf, *yr;
    cudaGetSymbolAddress((void**)&xr, g_xr);
    cudaGetSymbolAddress((void**)&wr, g_wr);
    cudaGetSymbolAddress((void**)&xf, g_xf);
    cudaGetSymbolAddress((void**)&wf, g_wf);
    cudaGetSymbolAddress((void**)&yf, g_yf);
    cudaGetSymbolAddress((void**)&yr, g_yr);

    cudaFuncSetAttribute(k_bingemm, cudaFuncAttributeMaxDynamicSharedMemorySize,
                         BG_SMEM_BYTES);

    // PDL launch config: consumer blocks arm on SMs during the producer's
    // tail wave and resume at completion (no per-boundary launch bubble).
    cudaLaunchAttribute pdl[1];
    pdl[0].id = cudaLaunchAttributeProgrammaticStreamSerialization;
    pdl[0].val.programmaticStreamSerializationAllowed = 1;
    cudaLaunchConfig_t cfg = {};
    cfg.attrs = pdl;
    cfg.numAttrs = 1;
    cfg.stream = 0;

    // Twiddle table (plain launch; everything after is PDL-chained)
    k_twd<<<1, 256>>>();

    // X path first, then W path (wf stays L2-hot for bingemm).
    cfg.gridDim = dim3(NIMG_X * 8); cfg.blockDim = dim3(256); cfg.dynamicSmemBytes = 0;
    cudaLaunchKernelEx(&cfg, k_rowfft, x, xr, NIMG_X);
    cfg.gridDim = dim3(KW, NIMG_X / 16);
    cudaLaunchKernelEx(&cfg, k_colfft, (const __half2*)xr, xf, NIMG_X);
    cfg.gridDim = dim3(NIMG_W * 8);
    cudaLaunchKernelEx(&cfg, k_rowfft, w, wr, NIMG_W);
    cfg.gridDim = dim3(KW, NIMG_W / 16);
    cudaLaunchKernelEx(&cfg, k_colfft, (const __half2*)wr, wf, NIMG_W);
    // Contraction: 16 bins/block, cp.async double-buffered pipeline
    cfg.gridDim = dim3((H * KW) / 16); cfg.dynamicSmemBytes = BG_SMEM_BYTES;
    cudaLaunchKernelEx(&cfg, k_bingemm, (const __half2*)xf, (const __half2*)wf, yf);
    // Inverse column FFT
    cfg.gridDim = dim3(KW, NIMG_Y / 16); cfg.dynamicSmemBytes = 0;
    cudaLaunchKernelEx(&cfg, k_icolfft, (const __half2*)yf, yr, NIMG_Y);
    // Packed inverse row FFT -> real output
    cfg.gridDim = dim3(NIMG_Y * 8);
    cudaLaunchKernelEx(&cfg, k_irowfft, (const __half2*)yr, out, NIMG_Y);
}

// round 17
// speedup vs baseline: 1.0286x; 1.0286x over previous
#include <cuda_runtime.h>
#include <cuda_fp16.h>
#include <cstddef>

// Problem constants
#define H 256
#define W 256
#define KW 129          // rfft bins along W
#define B_ 16
#define C_ 32
#define O_ 32
#define NIMG_X (B_*C_)  // 512
#define NIMG_W (O_*C_)  // 1024
#define NIMG_Y (B_*O_)  // 512

// ---------------- scratch (static device globals; allocation-free) ----------
__device__ __half2 g_xr[(size_t)KW * NIMG_X * H];
__device__ __half2 g_wr[(size_t)KW * NIMG_W * H];
__device__ __half2 g_xf[(size_t)H * KW * NIMG_X];
__device__ __half2 g_wf[(size_t)H * KW * NIMG_W];
__device__ __half2 g_yf[(size_t)H * KW * NIMG_Y];
__device__ __half2 g_yr[(size_t)KW * NIMG_Y * H];
__device__ float2  g_twd[256];   // W_256^i forward twiddles

__device__ __forceinline__ float2 cmulf(float2 a, float2 b) {
    return make_float2(fmaf(a.x, b.x, -a.y * b.y), fmaf(a.x, b.y, a.y * b.x));
}
__device__ __forceinline__ __half2 f2h(float2 v) { return __floats2half2_rn(v.x, v.y); }
__device__ __forceinline__ float2 h2f(__half2 v) { return __half22float2(v); }
__device__ __forceinline__ unsigned h2bits(__half2 v) { return *reinterpret_cast<unsigned*>(&v); }
__device__ __forceinline__ __half2 bits2h(unsigned u) { return *reinterpret_cast<__half2*>(&u); }
// streaming (last-use) half2 load
__device__ __forceinline__ __half2 ldcs_h2(const __half2* p) {
    unsigned u = __ldcs((const unsigned*)p);
    return bits2h(u);
}

// ---------------- K0: build twiddle table once per call ---------------------
__global__ void k_twd() {
    const int i = threadIdx.x;
    float sn, cs;
    sincosf(-6.283185307179586f * (float)i / 256.0f, &sn, &cs);
    g_twd[i] = make_float2(cs, sn);
}

// ---------------- in-register FFT-16 (Stockham radix-2, 4 stages) -----------
// j is compile-time constant per (stage, t); 15/32 butterflies have j==0
// (twiddle exactly (1,0)) -> emit plain moves instead of 4 FMAs.
template <bool INV>
__device__ __forceinline__ void fft16r(float2* a) {
    const float TR[8] = { 1.f,  0.9238795325112867f,  0.7071067811865476f,  0.3826834323650898f,
                          0.f, -0.3826834323650898f, -0.7071067811865476f, -0.9238795325112867f };
    const float TI[8] = { 0.f, -0.3826834323650898f, -0.7071067811865476f, -0.9238795325112867f,
                         -1.f, -0.9238795325112867f, -0.7071067811865476f, -0.3826834323650898f };
    float2 b[16];
    float2 *s = a, *d = b;
#pragma unroll
    for (int st = 0; st < 4; st++) {
        const int S = 1 << st;
#pragma unroll
        for (int t = 0; t < 8; t++) {
            const int j = t & ~(S - 1);
            float2 u = s[t], v = s[t + 8];
            float2 sum = make_float2(u.x + v.x, u.y + v.y);
            float2 dif = make_float2(u.x - v.x, u.y - v.y);
            d[t + j] = sum;
            if (j == 0) {
                d[t + j + S] = dif;                         // W^0 = (1,0): identity
            } else {
                const float wr = TR[j];
                const float wi = INV ? -TI[j] : TI[j];
                d[t + j + S] = make_float2(fmaf(dif.x, wr, -dif.y * wi),
                                           fmaf(dif.x, wi,  dif.y * wr));
            }
        }
        float2* tmp = s; s = d; d = tmp;
    }
}

// ---------------- FFT-256 on registers: 16 threads x 16 points --------------
template <bool INV>
__device__ __forceinline__ void fft256_regs(float2* a, float2* S,
                                            const float2* twd, int row, int t) {
    fft16r<INV>(a);
    // k2=0 multiplier is exactly (1,0) -> identity; skip (bit-identical).
#pragma unroll
    for (int k2 = 1; k2 < 16; k2++) {
        float2 w = twd[t * k2];
        if (INV) w.y = -w.y;
        a[k2] = cmulf(a[k2], w);
    }
    float2* Sr = S + row * 272;
    __syncwarp();
#pragma unroll
    for (int k2 = 0; k2 < 16; k2++) Sr[t * 17 + k2] = a[k2];
    __syncwarp();
#pragma unroll
    for (int n1 = 0; n1 < 16; n1++) a[n1] = Sr[n1 * 17 + t];
    __syncwarp();
    fft16r<INV>(a);
}

// ---------------- K1: packed row FFT (2 real rows per complex FFT) ----------
__global__ void __launch_bounds__(256) k_rowfft(const float* __restrict__ in,
                                                __half2* __restrict__ out, int nimg) {
    __shared__ float2 S[4352];
    __shared__ float2 twd[256];
    const int tid = threadIdx.x, row = tid >> 4, t = tid & 15;
    const int img = blockIdx.x >> 3, h0 = (blockIdx.x & 7) << 5;
    twd[tid] = g_twd[tid];
    const float* pa = in + ((size_t)img * H + h0 + 2 * row) * W + t;
    const float* pb = pa + W;
    float2 a[16];
#pragma unroll
    for (int q = 0; q < 16; q++) a[q] = make_float2(__ldcs(pa + q * 16), __ldcs(pb + q * 16));
    __syncthreads();
    fft256_regs<false>(a, S, twd, row, t);
    __syncthreads();
#pragma unroll
    for (int k1 = 0; k1 < 16; k1++) S[(k1 * 16 + t) * 17 + row] = a[k1];
    __syncthreads();
    const size_t ob = (size_t)img * H + h0;
    // Vectorized unpack: even/odd h-rows share Z/Zc -> one 8B store per pair.
    for (int i = tid; i < KW * 16; i += 256) {
        const int kw_ = i >> 4, r = i & 15;
        const float2 Z  = S[kw_ * 17 + r];
        const float2 Zc = S[((256 - kw_) & 255) * 17 + r];
        const __half2 he = f2h(make_float2((Z.x + Zc.x) * 0.5f, (Z.y - Zc.y) * 0.5f));
        const __half2 ho = f2h(make_float2((Z.y + Zc.y) * 0.5f, (Zc.x - Z.x) * 0.5f));
        uint2 v; v.x = h2bits(he); v.y = h2bits(ho);
        *reinterpret_cast<uint2*>(&out[(size_t)kw_ * nimg * H + ob + 2 * r]) = v;
    }
}

// ---------------- K2: column FFT -> bin-major [kh][KW][nimg] (fp16) ---------
__global__ void __launch_bounds__(256) k_colfft(const __half2* __restrict__ in,
                                                __half2* __restrict__ out, int nimg) {
    __shared__ float2 S[4352];
    __shared__ float2 twd[256];
    const int tid = threadIdx.x, row = tid >> 4, t = tid & 15;
    const int kw = blockIdx.x, img0 = blockIdx.y << 4;
    twd[tid] = g_twd[tid];
    const __half2* src = in + ((size_t)kw * nimg + img0 + row) * H + t;
    float2 a[16];
#pragma unroll
    for (int q = 0; q < 16; q++) a[q] = h2f(ldcs_h2(src + q * 16));
    __syncthreads();
    fft256_regs<false>(a, S, twd, row, t);
    __syncthreads();
#pragma unroll
    for (int k1 = 0; k1 < 16; k1++) S[(k1 * 16 + t) * 17 + row] = a[k1];
    __syncthreads();
    // Vectorized: 2 images per thread, one 8B store.
    for (int i = tid; i < 2048; i += 256) {
        const int kh = i >> 3, im = (i & 7) << 1;
        uint2 v;
        v.x = h2bits(f2h(S[kh * 17 + im]));
        v.y = h2bits(f2h(S[kh * 17 + im + 1]));
        *reinterpret_cast<uint2*>(&out[((size_t)kh * KW + kw) * nimg + img0 + im]) = v;
    }
}

// ---------------- K3: bingemm v5 — cp.async double-buffered pipeline --------
__device__ __forceinline__ void mma16816(float* c, const unsigned* a, unsigned b0, unsigned b1) {
    asm volatile("mma.sync.aligned.m16n8k16.row.col.f32.f16.f16.f32 "
                 "{%0,%1,%2,%3}, {%4,%5,%6,%7}, {%8,%9}, {%0,%1,%2,%3};"
                 : "+f"(c[0]), "+f"(c[1]), "+f"(c[2]), "+f"(c[3])
                 : "r"(a[0]), "r"(a[1]), "r"(a[2]), "r"(a[3]), "r"(b0), "r"(b1));
}

#define BG_XS_U 576          // per-bin x region (unsigned), pitch 36
#define BG_WS_U 1152         // per-bin w region (unsigned), pitch 36
#define BG_WS_BASE (2 * 4 * BG_XS_U)             // = 4608 unsigned
#define BG_SMEM_BYTES ((2 * 4 * (BG_XS_U + BG_WS_U)) * 4)   // 55296 B

__global__ void __launch_bounds__(256) k_bingemm(const __half2* __restrict__ xf,
                                                 const __half2* __restrict__ wf,
                                                 __half2* __restrict__ yf) {
    extern __shared__ __align__(16) unsigned sm[];
    unsigned* xs = sm;
    unsigned* ws = sm + BG_WS_BASE;
    const unsigned smem_base = (unsigned)__cvta_generic_to_shared(sm);
    const int tid = threadIdx.x;
    const size_t gbin0 = (size_t)blockIdx.x * 16;

    auto issue = [&](int ch) {
        const int buf = ch & 1;
        const char* xg = (const char*)(xf + (gbin0 + ch * 4) * NIMG_X);
        const char* wg = (const char*)(wf + (gbin0 + ch * 4) * NIMG_W);
        for (int i = tid; i < 512; i += 256) {
            const int lb = i >> 7, jj = (i & 127) << 2;
            const unsigned soff = ((buf * 4 + lb) * BG_XS_U + (jj >> 5) * 36 + (jj & 31)) * 4;
            asm volatile("cp.async.cg.shared.global [%0], [%1], 16;"
                         :: "r"(smem_base + soff), "l"(xg + lb * 2048 + jj * 4) : "memory");
        }
        for (int i = tid; i < 1024; i += 256) {
            const int lb = i >> 8, jj = (i & 255) << 2;
            const unsigned soff = (BG_WS_BASE + (buf * 4 + lb) * BG_WS_U
                                   + (jj >> 5) * 36 + (jj & 31)) * 4;
            asm volatile("cp.async.cg.shared.global [%0], [%1], 16;"
                         :: "r"(smem_base + soff), "l"(wg + lb * 4096 + jj * 4) : "memory");
        }
        asm volatile("cp.async.commit_group;" ::: "memory");
    };

    issue(0);
    issue(1);

    const int wp = tid >> 6;             // bin-in-chunk 0..3
    const int sub = (tid >> 5) & 1;      // which half of the ot tiles
    const int lane = tid & 31, r = lane >> 2, q = lane & 3;

    for (int ch = 0; ch < 4; ch++) {
        const int buf = ch & 1;
        if (ch < 3) asm volatile("cp.async.wait_group 1;" ::: "memory");
        else        asm volatile("cp.async.wait_group 0;" ::: "memory");
        __syncthreads();

        unsigned* X = xs + (buf * 4 + wp) * BG_XS_U;
        const unsigned* Wm = ws + (buf * 4 + wp) * BG_WS_U;
        float cre[2][4] = {{0}}, cim[2][4] = {{0}};
#pragma unroll
        for (int kc = 0; kc < 4; kc++) {
            unsigned a[4];
            a[0] = X[r * 36 + kc * 8 + q];
            a[1] = X[(r + 8) * 36 + kc * 8 + q];
            a[2] = X[r * 36 + kc * 8 + 4 + q];
            a[3] = X[(r + 8) * 36 + kc * 8 + 4 + q];
#pragma unroll
            for (int oti = 0; oti < 2; oti++) {
                const int ot = sub * 2 + oti;
                const unsigned w0 = Wm[(ot * 8 + r) * 36 + kc * 8 + q];
                const unsigned w1 = Wm[(ot * 8 + r) * 36 + kc * 8 + 4 + q];
                mma16816(cre[oti], a, w0 ^ 0x80000000u, w1 ^ 0x80000000u);  // (wr,-wi)
                mma16816(cim[oti], a, __byte_perm(w0, w0, 0x1032),          // (wi,wr)
                                       __byte_perm(w1, w1, 0x1032));
            }
        }
        __syncthreads();   // all fragment reads of this buffer done
        // Stage C into the (dead) x region of this buffer, stride 33.
#pragma unroll
        for (int oti = 0; oti < 2; oti++) {
            const int ot = sub * 2 + oti;
            const int o0 = ot * 8 + 2 * q;
            X[r * 33 + o0]           = h2bits(f2h(make_float2(cre[oti][0], cim[oti][0])));
            X[r * 33 + o0 + 1]       = h2bits(f2h(make_float2(cre[oti][1], cim[oti][1])));
            X[(r + 8) * 33 + o0]     = h2bits(f2h(make_float2(cre[oti][2], cim[oti][2])));
            X[(r + 8) * 33 + o0 + 1] = h2bits(f2h(make_float2(cre[oti][3], cim[oti][3])));
        }
        __syncthreads();
        unsigned* yg = (unsigned*)(yf + (gbin0 + ch * 4) * NIMG_Y);
        for (int i = tid; i < 512; i += 256) {
            const int lb = i >> 7, jj = (i & 127) << 2;
            const int base = (buf * 4 + lb) * BG_XS_U + (jj >> 5) * 33 + (jj & 31);
            uint4 v;
            v.x = xs[base];
            v.y = xs[base + 1];
            v.z = xs[base + 2];
            v.w = xs[base + 3];
            *reinterpret_cast<uint4*>(yg + lb * 512 + jj) = v;
        }
        __syncthreads();   // copy-out reads done before this buffer is refilled
        if (ch + 2 < 4) issue(ch + 2);
    }
}

// ---------------- K4: inverse column FFT -> [kw][nimg][h], scale 1/256 ------
__global__ void __launch_bounds__(256) k_icolfft(const __half2* __restrict__ in,
                                                 __half2* __restrict__ out, int nimg) {
    __shared__ float2 S[4352];
    __shared__ float2 twd[256];
    const int tid = threadIdx.x, row = tid >> 4, t = tid & 15;
    const int kw = blockIdx.x, img0 = blockIdx.y << 4;
    twd[tid] = g_twd[tid];
    // Vectorized 8B input loads (2 images per thread).
    for (int i = tid; i < 2048; i += 256) {
        const int kh = i >> 3, im = (i & 7) << 1;
        const uint2 u = __ldcs((const uint2*)(in + ((size_t)kh * KW + kw) * nimg + img0 + im));
        S[kh * 17 + im]     = h2f(bits2h(u.x));
        S[kh * 17 + im + 1] = h2f(bits2h(u.y));
    }
    __syncthreads();
    float2 a[16];
#pragma unroll
    for (int q = 0; q < 16; q++) a[q] = S[(q * 16 + t) * 17 + row];
    __syncthreads();
    fft256_regs<true>(a, S, twd, row, t);
    __syncthreads();
    const float sc = 1.0f / 256.0f;
#pragma unroll
    for (int k1 = 0; k1 < 16; k1++)
        S[row * 256 + k1 * 16 + t] = make_float2(a[k1].x * sc, a[k1].y * sc);
    __syncthreads();
    // Vectorized: 2 h per thread (16B smem read, 8B gmem store).
    for (int i = tid; i < 2048; i += 256) {
        const int im = i >> 7, h = (i & 127) << 1;
        const float4 vv = *reinterpret_cast<const float4*>(&S[im * 256 + h]);
        uint2 v;
        v.x = h2bits(f2h(make_float2(vv.x, vv.y)));
        v.y = h2bits(f2h(make_float2(vv.z, vv.w)));
        *reinterpret_cast<uint2*>(&out[((size_t)kw * nimg + img0 + im) * H + h]) = v;
    }
}

// ---------------- K5: packed inverse row FFT (2 real rows per iFFT) ---------
__global__ void __launch_bounds__(256) k_irowfft(const __half2* __restrict__ in,
                                                 float* __restrict__ out, int nimg) {
    __shared__ float2 S[4352];
    __shared__ float2 twd[256];
    const int tid = threadIdx.x, row = tid >> 4, t = tid & 15;
    const int img = blockIdx.x >> 3, h0 = (blockIdx.x & 7) << 5;
    twd[tid] = g_twd[tid];
    // Vectorized 8B input loads (2 hh per thread).
    for (int i = tid; i < KW * 16; i += 256) {
        const int kw_ = i >> 4, hh = (i & 15) << 1;
        const uint2 u = __ldcs((const uint2*)(in + (size_t)kw_ * nimg * H + (size_t)img * H + h0 + hh));
        S[kw_ * 33 + hh]     = h2f(bits2h(u.x));
        S[kw_ * 33 + hh + 1] = h2f(bits2h(u.y));
    }
    __syncthreads();
    float2 a[16];
#pragma unroll
    for (int q = 0; q < 16; q++) {
        const int n = q * 16 + t;
        if (n <= 128) {
            const float2 ya = S[n * 33 + 2 * row];
            const float2 yb = S[n * 33 + 2 * row + 1];
            a[q] = make_float2(ya.x - yb.y, ya.y + yb.x);        // Ya + i*Yb
        } else {
            const int m = 256 - n;
            const float2 ya = S[m * 33 + 2 * row];
            const float2 yb = S[m * 33 + 2 * row + 1];
            a[q] = make_float2(ya.x + yb.y, yb.x - ya.y);        // conj(Ya)+i*conj(Yb)
        }
    }
    __syncthreads();
    fft256_regs<true>(a, S, twd, row, t);
    __syncthreads();
    float* Sf = (float*)S;
    const float sc = 1.0f / 256.0f;
#pragma unroll
    for (int k1 = 0; k1 < 16; k1++) {
        const int idx = k1 * 16 + t;
        Sf[(2 * row) * 256 + idx]     = a[k1].x * sc;
        Sf[(2 * row + 1) * 256 + idx] = a[k1].y * sc;
    }
    __syncthreads();
    const size_t ob = ((size_t)img * H + h0) * W;
    // Vectorized 16B output stores.
    for (int i = tid; i < 2048; i += 256) {
        const int base = i << 2;
        const float4 v = *reinterpret_cast<const float4*>(&Sf[base]);
        __stcs((float4*)(out + ob + (size_t)(base >> 8) * W + (base & 255)), v);
    }
}

// ---------------------------------------------------------------------------
extern "C" void kernel_launch(void* const* d_in, const int* in_sizes, int n_in,
                              void* d_out, int out_size) {
    (void)in_sizes; (void)n_in; (void)out_size;
    const float* x = (const float*)d_in[0];   // (B,C,H,W)
    const float* w = (const float*)d_in[1];   // (O,C,H,W)
    float* out = (float*)d_out;               // (B,O,H,W)

    __half2 *xr, *wr, *xf, *wf, *yf, *yr;
    cudaGetSymbolAddress((void**)&xr, g_xr);
    cudaGetSymbolAddress((void**)&wr, g_wr);
    cudaGetSymbolAddress((void**)&xf, g_xf);
    cudaGetSymbolAddress((void**)&wf, g_wf);
    cudaGetSymbolAddress((void**)&yf, g_yf);
    cudaGetSymbolAddress((void**)&yr, g_yr);

    cudaFuncSetAttribute(k_bingemm, cudaFuncAttributeMaxDynamicSharedMemorySize,
                         BG_SMEM_BYTES);

    // Twiddle table (replaces per-block sincosf in every FFT kernel)
    k_twd<<<1, 256>>>();
    // X path first, then W path: wf (135MB ~ L2 capacity) is written
    // immediately before bingemm reads it -> the LARGER spectrum stays L2-hot
    // (sacrifices xf, only 68MB, to DRAM). xr/wr adjacency preserved.
    k_rowfft<<<NIMG_X * 8, 256>>>(x, xr, NIMG_X);
    k_colfft<<<dim3(KW, NIMG_X / 16), 256>>>(xr, xf, NIMG_X);
    k_rowfft<<<NIMG_W * 8, 256>>>(w, wr, NIMG_W);
    k_colfft<<<dim3(KW, NIMG_W / 16), 256>>>(wr, wf, NIMG_W);
    // Contraction: 16 bins/block, cp.async double-buffered pipeline
    k_bingemm<<<(H * KW) / 16, 256, BG_SMEM_BYTES>>>(xf, wf, yf);
    // Inverse column FFT (fp16 in/out)
    k_icolfft<<<dim3(KW, NIMG_Y / 16), 256>>>(yf, yr, NIMG_Y);
    // Packed inverse row FFT -> real output
    k_irowfft<<<NIMG_Y * 8, 256>>>(yr, out, NIMG_Y);
}